// round 14
// baseline (speedup 1.0000x reference)
#include <cuda_runtime.h>

// ---------------- problem constants ----------------
#define T_STEPS 131   // 128 story + 1 query + 2 empty
#define BSZ     64
#define EMB     128
#define HID     256
#define VOCAB   32000
#define MSTL    128
#define MSEL    24
#define QL      16

// ---------------- scratch ----------------
__device__ __align__(16) float d_X[129 * 8 * EMB * 8];   // [t][bt8][e][8b]
__device__ __align__(16) float d_H[2 * 8 * HID * 8];     // [buf2][bt8][k][8b]
#define NFLAGS (T_STEPS * 8 * 16)
__device__ unsigned d_flag[NFLAGS];

// ---------------- helpers ----------------
typedef unsigned long long u64;

__device__ __forceinline__ u64 pack2(float x, float y) {
    u64 r; asm("mov.b64 %0, {%1, %2};" : "=l"(r) : "f"(x), "f"(y)); return r;
}
__device__ __forceinline__ void ffma2(u64& acc, u64 a, u64 b) {
    asm("fma.rn.f32x2 %0, %1, %2, %0;" : "+l"(acc) : "l"(a), "l"(b));
}
__device__ __forceinline__ void lds_2x64(u64& p0, u64& p1, unsigned addr) {
    asm volatile("ld.shared.v2.u64 {%0, %1}, [%2];" : "=l"(p0), "=l"(p1) : "r"(addr));
}
__device__ __forceinline__ void sts_2x64(unsigned addr, u64 p0, u64 p1) {
    asm volatile("st.shared.v2.u64 [%0], {%1, %2};" :: "r"(addr), "l"(p0), "l"(p1));
}
__device__ __forceinline__ void unpack2(u64 p, float& x, float& y) {
    asm("mov.b64 {%0, %1}, %2;" : "=f"(x), "=f"(y) : "l"(p));
}
__device__ __forceinline__ void cp_async16(unsigned smem, const void* gptr) {
    asm volatile("cp.async.cg.shared.global [%0], [%1], 16;" :: "r"(smem), "l"(gptr));
}
__device__ __forceinline__ void cp_commit() { asm volatile("cp.async.commit_group;"); }
__device__ __forceinline__ void cp_waitg0() { asm volatile("cp.async.wait_group 0;"); }
__device__ __forceinline__ void cp_waitg1() { asm volatile("cp.async.wait_group 1;"); }
__device__ __forceinline__ void cp_waitg2() { asm volatile("cp.async.wait_group 2;"); }

__device__ __forceinline__ unsigned ld_acq(const unsigned* p) {
    unsigned v;
    asm volatile("ld.acquire.gpu.global.b32 %0, [%1];" : "=r"(v) : "l"(p));
    return v;
}
__device__ __forceinline__ void st_rel(unsigned* p, unsigned v) {
    asm volatile("st.release.gpu.global.b32 [%0], %1;" :: "l"(p), "r"(v));
}

__device__ __forceinline__ float sigf(float x) {
    return 1.0f / (1.0f + __expf(-x));
}
__device__ __forceinline__ float tanh_f(float x) {
    float a = fabsf(x);
    float e = __expf(-2.0f * a);
    float r = (1.0f - e) / (1.0f + e);
    return copysignf(r, x);
}

// ============================================================================
// Kernel 0: clear flags
// ============================================================================
__global__ void clear_flags_kernel() {
    int i = blockIdx.x * 256 + threadIdx.x;
    if (i < NFLAGS) d_flag[i] = 0;
}

// ============================================================================
// Kernel 1: embedding gather + position encoding -> d_X [t][bt8][e][8b]
// ============================================================================
__global__ void encode_kernel(const int* __restrict__ story,
                              const int* __restrict__ query,
                              const float* __restrict__ E) {
    int wid  = blockIdx.x * 8 + (threadIdx.x >> 5);
    int lane = threadIdx.x & 31;
    int b = wid / T_STEPS;
    int t = wid % T_STEPS;
    if (t > MSTL) return;
    int e0 = lane * 4;

    const float invE = 1.0f / (float)EMB;
    float k0 = (e0 + 1) * invE;
    float k1 = (e0 + 2) * invE;
    float k2 = (e0 + 3) * invE;
    float k3 = (e0 + 4) * invE;

    float4 acc = make_float4(0.f, 0.f, 0.f, 0.f);

    if (t < MSTL) {
        const int* toks = story + (b * MSTL + t) * MSEL;
#pragma unroll
        for (int s = 0; s < MSEL; ++s) {
            int tok = toks[s];
            float j = (s + 1) * (1.0f / 32.0f);
            float A = 1.0f - j, Bc = 1.0f - 2.0f * j;
            float4 ev = *(const float4*)(E + tok * EMB + e0);
            acc.x += ev.x * (A - k0 * Bc);
            acc.y += ev.y * (A - k1 * Bc);
            acc.z += ev.z * (A - k2 * Bc);
            acc.w += ev.w * (A - k3 * Bc);
        }
    } else {
        const int* toks = query + b * QL;
#pragma unroll
        for (int s = 0; s < QL; ++s) {
            int tok = toks[s];
            float j = (s + 1) * (1.0f / 32.0f);
            float A = 1.0f - j, Bc = 1.0f - 2.0f * j;
            float4 ev = *(const float4*)(E + tok * EMB + e0);
            acc.x += ev.x * (A - k0 * Bc);
            acc.y += ev.y * (A - k1 * Bc);
            acc.z += ev.z * (A - k2 * Bc);
            acc.w += ev.w * (A - k3 * Bc);
        }
    }
    float* dst = d_X + ((t * 8 + (b >> 3)) * EMB) * 8 + (b & 7);
    dst[(e0 + 0) * 8] = acc.x;
    dst[(e0 + 1) * 8] = acc.y;
    dst[(e0 + 2) * 8] = acc.z;
    dst[(e0 + 3) * 8] = acc.w;
}

// ============================================================================
// Kernel 2: persistent LSTM, TWO interleaved batch streams per CTA.
//   64 CTAs = 16 ht x 4 btp; streams A/B = bt 2*btp, 2*btp+1.
//   Per-stream protocol identical to R6 (flags + cp.async + release/acquire).
//   SMEM (bytes): XS[s][buf][4KB] 0..16K | HS[s][8KB] 16K..32K |
//                 PS[s][16KB] 32K..64K | BS 64K..64K+256
// ============================================================================
#define RGRID 64
#define RTHREADS 512
#define SM_XS 0
#define SM_HS 16384
#define SM_PS 32768
#define SM_BS 65536
#define LSTM_SMEM_BYTES (65536 + 256)

__global__ void __launch_bounds__(RTHREADS, 1)
lstm_kernel(const float* __restrict__ W_ih, const float* __restrict__ W_hh,
            const float* __restrict__ b_ih, const float* __restrict__ b_hh) {
    extern __shared__ float sm[];
    const unsigned smb = (unsigned)__cvta_generic_to_shared(sm);

    const int tid = threadIdx.x;
    const int btp = blockIdx.x & 3;
    const int ht  = blockIdx.x >> 2;
    const int btA = btp * 2, btB = btp * 2 + 1;
    const int kc  = tid >> 6;          // 0..7
    const int r   = tid & 63;          // g*16 + jj
    const int grow = (r >> 4) * 256 + ht * 16 + (r & 15);

    // ---- register weights (shared by both streams) ----
    float4 wih[4];    // W_ih[grow][kc*16 .. +16)
    float4 whh[8];    // W_hh[grow][kc*32 .. +32)
    {
        const float4* p = (const float4*)(W_ih + grow * EMB + kc * 16);
#pragma unroll
        for (int q = 0; q < 4; ++q) wih[q] = p[q];
        const float4* ph = (const float4*)(W_hh + grow * HID + kc * 32);
#pragma unroll
        for (int q = 0; q < 8; ++q) whh[q] = ph[q];
    }
    if (tid < 64) {
        int gr = (tid >> 4) * 256 + ht * 16 + (tid & 15);
        sm[SM_BS / 4 + tid] = b_ih[gr] + b_hh[gr];
    }

    const unsigned xsA = smb + SM_XS;            // + (t&1)*4096
    const unsigned xsB = smb + SM_XS + 8192;
    const unsigned hsA = smb + SM_HS;
    const unsigned hsB = smb + SM_HS + 8192;
    const unsigned psA = smb + SM_PS;
    const unsigned psB = smb + SM_PS + 16384;
    const unsigned hbA = hsA + kc * 1024;
    const unsigned hbB = hsB + kc * 1024;
    const unsigned pbA = psA + tid * 32;
    const unsigned pbB = psB + tid * 32;
    float* bshp = sm + SM_BS / 4;

    const int w    = tid >> 5;   // warp id 0..15
    const int lane = tid & 31;

    // prologue: prefetch x(0) for both streams [group X(0)]
    if (tid < 256) {
        cp_async16(xsA + tid * 16, d_X + btA * (EMB * 8) + tid * 4);
        cp_async16(xsB + tid * 16, d_X + btB * (EMB * 8) + tid * 4);
    }
    cp_commit();

    float cA = 0.0f, cB = 0.0f;
    __syncthreads();   // bsh ready

    for (int t = 0; t < T_STEPS; ++t) {
        u64 aA0 = 0, aA1 = 0, aA2 = 0, aA3 = 0;
        u64 aB0 = 0, aB1 = 0, aB2 = 0, aB3 = 0;

        if (t <= MSTL) {
            cp_waitg0();                 // drains X(t) (only group pending)
            __syncthreads();             // bar1: x(t) visible
        }

        // ---- x-GEMMs (fillers before the polls) ----
        if (t <= MSTL) {
            const unsigned xoff = (t & 1) ? 4096u : 0u;
            {
                const unsigned xb = xsA + xoff + kc * 512;
#pragma unroll
                for (int q = 0; q < 4; ++q) {
                    float4 w4 = wih[q];
#pragma unroll
                    for (int cc = 0; cc < 4; ++cc) {
                        float wv = (cc == 0) ? w4.x : (cc == 1) ? w4.y : (cc == 2) ? w4.z : w4.w;
                        u64 wd = pack2(wv, wv);
                        u64 p0, p1, p2, p3;
                        unsigned ad = xb + (q * 4 + cc) * 32;
                        lds_2x64(p0, p1, ad);
                        lds_2x64(p2, p3, ad + 16);
                        ffma2(aA0, wd, p0); ffma2(aA1, wd, p1);
                        ffma2(aA2, wd, p2); ffma2(aA3, wd, p3);
                    }
                }
            }
            {
                const unsigned xb = xsB + xoff + kc * 512;
#pragma unroll
                for (int q = 0; q < 4; ++q) {
                    float4 w4 = wih[q];
#pragma unroll
                    for (int cc = 0; cc < 4; ++cc) {
                        float wv = (cc == 0) ? w4.x : (cc == 1) ? w4.y : (cc == 2) ? w4.z : w4.w;
                        u64 wd = pack2(wv, wv);
                        u64 p0, p1, p2, p3;
                        unsigned ad = xb + (q * 4 + cc) * 32;
                        lds_2x64(p0, p1, ad);
                        lds_2x64(p2, p3, ad + 16);
                        ffma2(aB0, wd, p0); ffma2(aB1, wd, p1);
                        ffma2(aB2, wd, p2); ffma2(aB3, wd, p3);
                    }
                }
            }
        }

        // ---- poll + stage stream A   [group A] ----
        if (t > 0) {
            const unsigned* fp = &d_flag[((t - 1) * 8 + btA) * 16 + w];
            while (ld_acq(fp) == 0) { }
            const float* src = d_H + (((t - 1) & 1) * 8 + btA) * (HID * 8)
                               + w * 128 + lane * 4;
            cp_async16(hsA + w * 512 + lane * 16, src);
        }
        cp_commit();   // group A

        // ---- poll + stage stream B   [group B] ----
        if (t > 0) {
            const unsigned* fp = &d_flag[((t - 1) * 8 + btB) * 16 + w];
            while (ld_acq(fp) == 0) { }
            const float* src = d_H + (((t - 1) & 1) * 8 + btB) * (HID * 8)
                               + w * 128 + lane * 4;
            cp_async16(hsB + w * 512 + lane * 16, src);
        }
        cp_commit();   // group B

        // ---- x(t+1) prefetch LAST so it stays outstanding  [group X(t+1)] ----
        if (t < MSTL && tid < 256) {
            const unsigned xoff = ((t + 1) & 1) ? 4096u : 0u;
            cp_async16(xsA + xoff + tid * 16,
                       d_X + (((t + 1) * 8 + btA) * EMB) * 8 + tid * 4);
            cp_async16(xsB + xoff + tid * 16,
                       d_X + (((t + 1) * 8 + btB) * EMB) * 8 + tid * 4);
        }
        cp_commit();   // group X(t+1)

        if (t > 0) {
            cp_waitg2();                 // drains group A (B + X remain)
            __syncthreads();             // barA: hsA visible

            // ---- h-GEMM A (overlaps group B in flight) ----
#pragma unroll
            for (int q = 0; q < 8; ++q) {
                float4 w4 = whh[q];
#pragma unroll
                for (int cc = 0; cc < 4; ++cc) {
                    float wv = (cc == 0) ? w4.x : (cc == 1) ? w4.y : (cc == 2) ? w4.z : w4.w;
                    u64 wd = pack2(wv, wv);
                    u64 p0, p1, p2, p3;
                    unsigned ad = hbA + (q * 4 + cc) * 32;
                    lds_2x64(p0, p1, ad);
                    lds_2x64(p2, p3, ad + 16);
                    ffma2(aA0, wd, p0); ffma2(aA1, wd, p1);
                    ffma2(aA2, wd, p2); ffma2(aA3, wd, p3);
                }
            }
            sts_2x64(pbA, aA0, aA1);
            sts_2x64(pbA + 16, aA2, aA3);

            cp_waitg1();                 // drains group B (X remains)
            __syncthreads();             // barB: hsB visible

            // ---- h-GEMM B ----
#pragma unroll
            for (int q = 0; q < 8; ++q) {
                float4 w4 = whh[q];
#pragma unroll
                for (int cc = 0; cc < 4; ++cc) {
                    float wv = (cc == 0) ? w4.x : (cc == 1) ? w4.y : (cc == 2) ? w4.z : w4.w;
                    u64 wd = pack2(wv, wv);
                    u64 p0, p1, p2, p3;
                    unsigned ad = hbB + (q * 4 + cc) * 32;
                    lds_2x64(p0, p1, ad);
                    lds_2x64(p2, p3, ad + 16);
                    ffma2(aB0, wd, p0); ffma2(aB1, wd, p1);
                    ffma2(aB2, wd, p2); ffma2(aB3, wd, p3);
                }
            }
        } else {
            cp_waitg2();                 // t==0: drain empty A
            __syncthreads();
            sts_2x64(pbA, aA0, aA1);
            sts_2x64(pbA + 16, aA2, aA3);
            cp_waitg1();                 // drain empty B
            __syncthreads();
        }
        sts_2x64(pbB, aB0, aB1);
        sts_2x64(pbB + 16, aB2, aB3);
        __syncthreads();                 // bar_psh

        // ---- reduce + gates + publish (both streams) ----
        if (tid < 128) {
            const int j2 = tid >> 3, b = tid & 7;
            float vA[4], vB[4];
#pragma unroll
            for (int g = 0; g < 4; ++g) {
                int rr = g * 16 + j2;
                float sA = bshp[rr], sB = bshp[rr];
#pragma unroll
                for (int k8 = 0; k8 < 8; ++k8) {
                    sA += sm[(SM_PS / 4) + k8 * 512 + rr * 8 + b];
                    sB += sm[(SM_PS / 4) + 4096 + k8 * 512 + rr * 8 + b];
                }
                vA[g] = sA; vB[g] = sB;
            }
            {
                float ig = sigf(vA[0]), fg = sigf(vA[1]);
                float gv = tanh_f(vA[2]), og = sigf(vA[3]);
                cA = fg * cA + ig * gv;
                float h = og * tanh_f(cA);
                __stcg(&d_H[((t & 1) * 8 + btA) * (HID * 8) + (ht * 16 + j2) * 8 + b], h);
            }
            {
                float ig = sigf(vB[0]), fg = sigf(vB[1]);
                float gv = tanh_f(vB[2]), og = sigf(vB[3]);
                cB = fg * cB + ig * gv;
                float h = og * tanh_f(cB);
                __stcg(&d_H[((t & 1) * 8 + btB) * (HID * 8) + (ht * 16 + j2) * 8 + b], h);
            }
        }
        __syncthreads();                 // bar_end: stores ordered before release

        if (tid == 0 && t < T_STEPS - 1) {
            st_rel(&d_flag[(t * 8 + btA) * 16 + ht], 1u);
            st_rel(&d_flag[(t * 8 + btB) * 16 + ht], 1u);
        }
    }
}

// ============================================================================
// Kernel 3: logits = h @ lin_W.T + lin_b   (R12 variant, best measured)
// ============================================================================
__global__ void __launch_bounds__(256, 1)
out_kernel(const float* __restrict__ lin_W, const float* __restrict__ lin_b,
           float* __restrict__ out) {
    extern __shared__ float hsh[];  // [256 k][64 b], 64 KB
    const int tid = threadIdx.x;
    {
        // d_H buf0 [bt8][k256][8b] -> hsh [k][64b]
        const float4* src = (const float4*)d_H;
        for (int idx4 = tid; idx4 < 4096; idx4 += 256) {
            int btx = idx4 >> 9, k = (idx4 >> 1) & 255, half = idx4 & 1;
            float4 v = src[idx4];
            *(float4*)(hsh + k * 64 + btx * 8 + half * 4) = v;
        }
    }
    __syncthreads();

    const int cg = tid & 63;          // column group (4 cols)
    const int bq = tid >> 6;          // batch quarter (16 batches)
    const int v0 = blockIdx.x * 256 + cg * 4;
    const unsigned hb = (unsigned)__cvta_generic_to_shared(hsh) + bq * 64;

    u64 acc[4][8];
#pragma unroll
    for (int cidx = 0; cidx < 4; ++cidx) {
        float bb = lin_b[v0 + cidx];
        u64 bp = pack2(bb, bb);
#pragma unroll
        for (int p = 0; p < 8; ++p) acc[cidx][p] = bp;
    }

    const float4* wp0 = (const float4*)(lin_W + (v0 + 0) * HID);
    const float4* wp1 = (const float4*)(lin_W + (v0 + 1) * HID);
    const float4* wp2 = (const float4*)(lin_W + (v0 + 2) * HID);
    const float4* wp3 = (const float4*)(lin_W + (v0 + 3) * HID);

    float4 wA[4], wB[4];
    wA[0] = wp0[0]; wA[1] = wp1[0]; wA[2] = wp2[0]; wA[3] = wp3[0];

#pragma unroll 2
    for (int kk = 0; kk < HID / 4; ++kk) {
        float4* cur = (kk & 1) ? wB : wA;
        float4* nxt = (kk & 1) ? wA : wB;
        if (kk + 1 < HID / 4) {
            nxt[0] = wp0[kk + 1]; nxt[1] = wp1[kk + 1];
            nxt[2] = wp2[kk + 1]; nxt[3] = wp3[kk + 1];
        }
#pragma unroll
        for (int cc = 0; cc < 4; ++cc) {
            int k = kk * 4 + cc;
            u64 q[8];
            unsigned base = hb + (unsigned)k * 256;
            lds_2x64(q[0], q[1], base);
            lds_2x64(q[2], q[3], base + 16);
            lds_2x64(q[4], q[5], base + 32);
            lds_2x64(q[6], q[7], base + 48);
#pragma unroll
            for (int cidx = 0; cidx < 4; ++cidx) {
                float wv = (cc == 0) ? cur[cidx].x : (cc == 1) ? cur[cidx].y
                         : (cc == 2) ? cur[cidx].z : cur[cidx].w;
                u64 wd = pack2(wv, wv);
#pragma unroll
                for (int p = 0; p < 8; ++p) ffma2(acc[cidx][p], wd, q[p]);
            }
        }
    }

    float f[4][16];
#pragma unroll
    for (int cidx = 0; cidx < 4; ++cidx)
#pragma unroll
        for (int p = 0; p < 8; ++p)
            unpack2(acc[cidx][p], f[cidx][2 * p], f[cidx][2 * p + 1]);

#pragma unroll
    for (int bl = 0; bl < 16; ++bl) {
        float4 o = make_float4(f[0][bl], f[1][bl], f[2][bl], f[3][bl]);
        *(float4*)(out + (bq * 16 + bl) * VOCAB + v0) = o;
    }
}

// ============================================================================
// launch
// ============================================================================
extern "C" void kernel_launch(void* const* d_in, const int* in_sizes, int n_in,
                              void* d_out, int out_size) {
    const int*   story  = (const int*)d_in[0];
    const int*   query  = (const int*)d_in[1];
    const float* E      = (const float*)d_in[2];
    const float* W_ih   = (const float*)d_in[3];
    const float* W_hh   = (const float*)d_in[4];
    const float* b_ih   = (const float*)d_in[5];
    const float* b_hh   = (const float*)d_in[6];
    const float* lin_W  = (const float*)d_in[7];
    const float* lin_b  = (const float*)d_in[8];
    float*       out    = (float*)d_out;

    cudaFuncSetAttribute(lstm_kernel, cudaFuncAttributeMaxDynamicSharedMemorySize,
                         LSTM_SMEM_BYTES);
    cudaFuncSetAttribute(out_kernel, cudaFuncAttributeMaxDynamicSharedMemorySize,
                         HID * BSZ * 4);

    clear_flags_kernel<<<(NFLAGS + 255) / 256, 256>>>();
    encode_kernel<<<(T_STEPS * BSZ) / 8, 256>>>(story, query, E);
    lstm_kernel<<<RGRID, RTHREADS, LSTM_SMEM_BYTES>>>(W_ih, W_hh, b_ih, b_hh);
    out_kernel<<<VOCAB / 256, 256, HID * BSZ * 4>>>(lin_W, lin_b, out);
}

// round 15
// speedup vs baseline: 1.7176x; 1.7176x over previous
#include <cuda_runtime.h>

// ---------------- problem constants ----------------
#define T_STEPS 131   // 128 story + 1 query + 2 empty
#define BSZ     64
#define EMB     128
#define HID     256
#define VOCAB   32000
#define MSTL    128
#define MSEL    24
#define QL      16

// ---------------- scratch ----------------
__device__ __align__(16) float d_X[129 * 8 * EMB * 8];   // [t][bt8][e][8b]
__device__ __align__(16) float d_H[2 * 8 * HID * 8];     // [buf2][bt8][k][8b]
#define NFLAGS (T_STEPS * 8 * 16)
__device__ unsigned d_flag[NFLAGS];

// ---------------- helpers ----------------
typedef unsigned long long u64;

__device__ __forceinline__ u64 pack2(float x, float y) {
    u64 r; asm("mov.b64 %0, {%1, %2};" : "=l"(r) : "f"(x), "f"(y)); return r;
}
__device__ __forceinline__ void ffma2(u64& acc, u64 a, u64 b) {
    asm("fma.rn.f32x2 %0, %1, %2, %0;" : "+l"(acc) : "l"(a), "l"(b));
}
__device__ __forceinline__ void lds_2x64(u64& p0, u64& p1, unsigned addr) {
    asm volatile("ld.shared.v2.u64 {%0, %1}, [%2];" : "=l"(p0), "=l"(p1) : "r"(addr));
}
__device__ __forceinline__ void sts_2x64(unsigned addr, u64 p0, u64 p1) {
    asm volatile("st.shared.v2.u64 [%0], {%1, %2};" :: "r"(addr), "l"(p0), "l"(p1));
}
__device__ __forceinline__ void unpack2(u64 p, float& x, float& y) {
    asm("mov.b64 {%0, %1}, %2;" : "=f"(x), "=f"(y) : "l"(p));
}
__device__ __forceinline__ void cp_async16(unsigned smem, const void* gptr) {
    asm volatile("cp.async.cg.shared.global [%0], [%1], 16;" :: "r"(smem), "l"(gptr));
}
__device__ __forceinline__ void cp_commit() { asm volatile("cp.async.commit_group;"); }
__device__ __forceinline__ void cp_wait0()  { asm volatile("cp.async.wait_group 0;"); }

__device__ __forceinline__ unsigned ld_acq(const unsigned* p) {
    unsigned v;
    asm volatile("ld.acquire.gpu.global.b32 %0, [%1];" : "=r"(v) : "l"(p));
    return v;
}
__device__ __forceinline__ void st_rel(unsigned* p, unsigned v) {
    asm volatile("st.release.gpu.global.b32 [%0], %1;" :: "l"(p), "r"(v));
}
__device__ __forceinline__ void bar_pair(int id) {
    asm volatile("bar.sync %0, 64;" :: "r"(id) : "memory");
}

__device__ __forceinline__ float sigf(float x) {
    return 1.0f / (1.0f + __expf(-x));
}
__device__ __forceinline__ float tanh_f(float x) {
    float a = fabsf(x);
    float e = __expf(-2.0f * a);
    float r = (1.0f - e) / (1.0f + e);
    return copysignf(r, x);
}

// ============================================================================
// Kernel 0: clear flags (graph replays must start from zero)
// ============================================================================
__global__ void clear_flags_kernel() {
    int i = blockIdx.x * 256 + threadIdx.x;
    if (i < NFLAGS) d_flag[i] = 0;
}

// ============================================================================
// Kernel 1: embedding gather + position encoding -> d_X [t][bt8][e][8b]
// ============================================================================
__global__ void encode_kernel(const int* __restrict__ story,
                              const int* __restrict__ query,
                              const float* __restrict__ E) {
    int wid  = blockIdx.x * 8 + (threadIdx.x >> 5);
    int lane = threadIdx.x & 31;
    int b = wid / T_STEPS;
    int t = wid % T_STEPS;
    if (t > MSTL) return;
    int e0 = lane * 4;

    const float invE = 1.0f / (float)EMB;
    float k0 = (e0 + 1) * invE;
    float k1 = (e0 + 2) * invE;
    float k2 = (e0 + 3) * invE;
    float k3 = (e0 + 4) * invE;

    float4 acc = make_float4(0.f, 0.f, 0.f, 0.f);

    if (t < MSTL) {
        const int* toks = story + (b * MSTL + t) * MSEL;
#pragma unroll
        for (int s = 0; s < MSEL; ++s) {
            int tok = toks[s];
            float j = (s + 1) * (1.0f / 32.0f);
            float A = 1.0f - j, Bc = 1.0f - 2.0f * j;
            float4 ev = *(const float4*)(E + tok * EMB + e0);
            acc.x += ev.x * (A - k0 * Bc);
            acc.y += ev.y * (A - k1 * Bc);
            acc.z += ev.z * (A - k2 * Bc);
            acc.w += ev.w * (A - k3 * Bc);
        }
    } else {
        const int* toks = query + b * QL;
#pragma unroll
        for (int s = 0; s < QL; ++s) {
            int tok = toks[s];
            float j = (s + 1) * (1.0f / 32.0f);
            float A = 1.0f - j, Bc = 1.0f - 2.0f * j;
            float4 ev = *(const float4*)(E + tok * EMB + e0);
            acc.x += ev.x * (A - k0 * Bc);
            acc.y += ev.y * (A - k1 * Bc);
            acc.z += ev.z * (A - k2 * Bc);
            acc.w += ev.w * (A - k3 * Bc);
        }
    }
    float* dst = d_X + ((t * 8 + (b >> 3)) * EMB) * 8 + (b & 7);
    dst[(e0 + 0) * 8] = acc.x;
    dst[(e0 + 1) * 8] = acc.y;
    dst[(e0 + 2) * 8] = acc.z;
    dst[(e0 + 3) * 8] = acc.w;
}

// ============================================================================
// Kernel 2: persistent LSTM recurrence — R6 flag exchange + PAIR-LOCAL gating.
//   128 CTAs = 16 ht x 8 bt, 512 threads: kc=tid>>6 (0..7), r=tid&63.
//   Key fact: thread kc reads only h blocks {2kc, 2kc+1}, which are staged
//   exactly by its own warp-pair {2kc, 2kc+1}. So the post-exchange gate is a
//   64-thread named barrier per pair, NOT a CTA barrier: ready pairs start
//   their h-GEMM while late pairs still wait on slow producers.
// ============================================================================
#define RGRID 128
#define RTHREADS 512

__global__ void __launch_bounds__(RTHREADS, 1)
lstm_kernel(const float* __restrict__ W_ih, const float* __restrict__ W_hh,
            const float* __restrict__ b_ih, const float* __restrict__ b_hh) {
    __shared__ __align__(16) float xsh[2][EMB * 8];   // 2 x 4KB, [e][8b]
    __shared__ __align__(16) float hsh[HID * 8];      // 8KB, [k][8b]
    __shared__ __align__(16) float psh[512 * 8];      // 16KB partials
    __shared__ float bsh[64];

    const int tid = threadIdx.x;
    const int bt  = blockIdx.x & 7;
    const int ht  = blockIdx.x >> 3;
    const int kc  = tid >> 6;          // 0..7  (== pair id)
    const int r   = tid & 63;          // g*16 + jj
    const int grow = (r >> 4) * 256 + ht * 16 + (r & 15);

    // ---- register-resident weight slices ----
    float4 wih[4];    // W_ih[grow][kc*16 .. +16)
    float4 whh[8];    // W_hh[grow][kc*32 .. +32)
    {
        const float4* p = (const float4*)(W_ih + grow * EMB + kc * 16);
#pragma unroll
        for (int q = 0; q < 4; ++q) wih[q] = p[q];
        const float4* ph = (const float4*)(W_hh + grow * HID + kc * 32);
#pragma unroll
        for (int q = 0; q < 8; ++q) whh[q] = ph[q];
    }
    if (tid < 64) {
        int gr = (tid >> 4) * 256 + ht * 16 + (tid & 15);
        bsh[tid] = b_ih[gr] + b_hh[gr];
    }

    const unsigned xs0   = (unsigned)__cvta_generic_to_shared(&xsh[0][0]);
    const unsigned hsb   = (unsigned)__cvta_generic_to_shared(hsh);
    const unsigned hbase = hsb + kc * 1024;
    const unsigned pbase = (unsigned)__cvta_generic_to_shared(psh) + tid * 32;

    const int w    = tid >> 5;   // warp id 0..15 (stages producer w's block)
    const int lane = tid & 31;

    // prefetch x(0)
    if (tid < 256) cp_async16(xs0 + tid * 16, d_X + bt * (EMB * 8) + tid * 4);
    cp_commit();

    float c = 0.0f;
    __syncthreads();   // bsh ready

    for (int t = 0; t < T_STEPS; ++t) {
        u64 a0 = 0, a1 = 0, a2 = 0, a3 = 0;

        if (t <= MSTL) {
            cp_wait0();
            __syncthreads();                        // bar1: x(t) visible CTA-wide
            if (t < MSTL) {
                if (tid < 256)
                    cp_async16(xs0 + (((t + 1) & 1) ? 4096 : 0) + tid * 16,
                               d_X + (((t + 1) * 8 + bt) * EMB) * 8 + tid * 4);
                cp_commit();
            }
            // ---- x-part GEMM (latency filler before the flag wait) ----
            const unsigned xb = xs0 + ((t & 1) ? 4096 : 0) + kc * 512;
#pragma unroll
            for (int q = 0; q < 4; ++q) {
                float4 w4 = wih[q];
#pragma unroll
                for (int cc = 0; cc < 4; ++cc) {
                    float wv = (cc == 0) ? w4.x : (cc == 1) ? w4.y : (cc == 2) ? w4.z : w4.w;
                    u64 wd = pack2(wv, wv);
                    u64 p0, p1, p2, p3;
                    unsigned ad = xb + (q * 4 + cc) * 32;
                    lds_2x64(p0, p1, ad);
                    lds_2x64(p2, p3, ad + 16);
                    ffma2(a0, wd, p0); ffma2(a1, wd, p1);
                    ffma2(a2, wd, p2); ffma2(a3, wd, p3);
                }
            }
        }

        if (t > 0) {
            // ---- exchange: warp w waits on producer w, stages its 512B
            //      block, then gates ONLY with its pair partner. ----
            if (w != ht) {
                const unsigned* fp = &d_flag[((t - 1) * 8 + bt) * 16 + w];
                while (ld_acq(fp) == 0) { }
                const float* src = d_H + (((t - 1) & 1) * 8 + bt) * (HID * 8)
                                   + w * 128 + lane * 4;
                cp_async16(hsb + w * 512 + lane * 16, src);
            }
            cp_commit();
            cp_wait0();                  // this warp's block performed
            bar_pair(1 + kc);            // pair {2kc,2kc+1}: both blocks visible

            // ---- h-part GEMM on k [kc*32, kc*32+32) = blocks 2kc,2kc+1 ----
#pragma unroll
            for (int q = 0; q < 8; ++q) {
                float4 w4 = whh[q];
#pragma unroll
                for (int cc = 0; cc < 4; ++cc) {
                    float wv = (cc == 0) ? w4.x : (cc == 1) ? w4.y : (cc == 2) ? w4.z : w4.w;
                    u64 wd = pack2(wv, wv);
                    u64 p0, p1, p2, p3;
                    unsigned ad = hbase + (q * 4 + cc) * 32;
                    lds_2x64(p0, p1, ad);
                    lds_2x64(p2, p3, ad + 16);
                    ffma2(a0, wd, p0); ffma2(a1, wd, p1);
                    ffma2(a2, wd, p2); ffma2(a3, wd, p3);
                }
            }
        }

        sts_2x64(pbase, a0, a1);
        sts_2x64(pbase + 16, a2, a3);
        __syncthreads();                 // bar2: all partials in psh

        // ---- reduce + gates + state update + h publish ----
        if (tid < 128) {
            const int j2 = tid >> 3, b = tid & 7;
            float v[4];
#pragma unroll
            for (int g = 0; g < 4; ++g) {
                int rr = g * 16 + j2;
                float s = bsh[rr];
#pragma unroll
                for (int k8 = 0; k8 < 8; ++k8) s += psh[k8 * 512 + rr * 8 + b];
                v[g] = s;
            }
            float ig = sigf(v[0]);
            float fg = sigf(v[1]);
            float gv = tanh_f(v[2]);
            float og = sigf(v[3]);
            c = fg * c + ig * gv;
            float h = og * tanh_f(c);
            hsh[ht * 128 + j2 * 8 + b] = h;   // own-block local publish
            __stcg(&d_H[((t & 1) * 8 + bt) * (HID * 8) + (ht * 16 + j2) * 8 + b], h);
        }
        __syncthreads();                 // bar3: h stores ordered before release

        if (tid == 0 && t < T_STEPS - 1)
            st_rel(&d_flag[(t * 8 + bt) * 16 + ht], 1u);
    }
}

// ============================================================================
// Kernel 3: logits = h @ lin_W.T + lin_b   (R12 variant — best measured)
// ============================================================================
__global__ void __launch_bounds__(256, 1)
out_kernel(const float* __restrict__ lin_W, const float* __restrict__ lin_b,
           float* __restrict__ out) {
    extern __shared__ float hsh[];  // [256 k][64 b], 64 KB
    const int tid = threadIdx.x;
    {
        // d_H buf0 [bt8][k256][8b] -> hsh [k][64b]
        const float4* src = (const float4*)d_H;
        for (int idx4 = tid; idx4 < 4096; idx4 += 256) {
            int btx = idx4 >> 9, k = (idx4 >> 1) & 255, half = idx4 & 1;
            float4 v = src[idx4];
            *(float4*)(hsh + k * 64 + btx * 8 + half * 4) = v;
        }
    }
    __syncthreads();

    const int cg = tid & 63;          // column group (4 cols)
    const int bq = tid >> 6;          // batch quarter (16 batches)
    const int v0 = blockIdx.x * 256 + cg * 4;
    const unsigned hb = (unsigned)__cvta_generic_to_shared(hsh) + bq * 64;

    u64 acc[4][8];
#pragma unroll
    for (int cidx = 0; cidx < 4; ++cidx) {
        float bb = lin_b[v0 + cidx];
        u64 bp = pack2(bb, bb);
#pragma unroll
        for (int p = 0; p < 8; ++p) acc[cidx][p] = bp;
    }

    const float4* wp0 = (const float4*)(lin_W + (v0 + 0) * HID);
    const float4* wp1 = (const float4*)(lin_W + (v0 + 1) * HID);
    const float4* wp2 = (const float4*)(lin_W + (v0 + 2) * HID);
    const float4* wp3 = (const float4*)(lin_W + (v0 + 3) * HID);

    float4 wA[4], wB[4];
    wA[0] = wp0[0]; wA[1] = wp1[0]; wA[2] = wp2[0]; wA[3] = wp3[0];

#pragma unroll 2
    for (int kk = 0; kk < HID / 4; ++kk) {
        float4* cur = (kk & 1) ? wB : wA;
        float4* nxt = (kk & 1) ? wA : wB;
        if (kk + 1 < HID / 4) {
            nxt[0] = wp0[kk + 1]; nxt[1] = wp1[kk + 1];
            nxt[2] = wp2[kk + 1]; nxt[3] = wp3[kk + 1];
        }
#pragma unroll
        for (int cc = 0; cc < 4; ++cc) {
            int k = kk * 4 + cc;
            u64 q[8];
            unsigned base = hb + (unsigned)k * 256;
            lds_2x64(q[0], q[1], base);
            lds_2x64(q[2], q[3], base + 16);
            lds_2x64(q[4], q[5], base + 32);
            lds_2x64(q[6], q[7], base + 48);
#pragma unroll
            for (int cidx = 0; cidx < 4; ++cidx) {
                float wv = (cc == 0) ? cur[cidx].x : (cc == 1) ? cur[cidx].y
                         : (cc == 2) ? cur[cidx].z : cur[cidx].w;
                u64 wd = pack2(wv, wv);
#pragma unroll
                for (int p = 0; p < 8; ++p) ffma2(acc[cidx][p], wd, q[p]);
            }
        }
    }

    float f[4][16];
#pragma unroll
    for (int cidx = 0; cidx < 4; ++cidx)
#pragma unroll
        for (int p = 0; p < 8; ++p)
            unpack2(acc[cidx][p], f[cidx][2 * p], f[cidx][2 * p + 1]);

#pragma unroll
    for (int bl = 0; bl < 16; ++bl) {
        float4 o = make_float4(f[0][bl], f[1][bl], f[2][bl], f[3][bl]);
        *(float4*)(out + (bq * 16 + bl) * VOCAB + v0) = o;
    }
}

// ============================================================================
// launch
// ============================================================================
extern "C" void kernel_launch(void* const* d_in, const int* in_sizes, int n_in,
                              void* d_out, int out_size) {
    const int*   story  = (const int*)d_in[0];
    const int*   query  = (const int*)d_in[1];
    const float* E      = (const float*)d_in[2];
    const float* W_ih   = (const float*)d_in[3];
    const float* W_hh   = (const float*)d_in[4];
    const float* b_ih   = (const float*)d_in[5];
    const float* b_hh   = (const float*)d_in[6];
    const float* lin_W  = (const float*)d_in[7];
    const float* lin_b  = (const float*)d_in[8];
    float*       out    = (float*)d_out;

    cudaFuncSetAttribute(out_kernel, cudaFuncAttributeMaxDynamicSharedMemorySize,
                         HID * BSZ * 4);

    clear_flags_kernel<<<(NFLAGS + 255) / 256, 256>>>();
    encode_kernel<<<(T_STEPS * BSZ) / 8, 256>>>(story, query, E);
    lstm_kernel<<<RGRID, RTHREADS>>>(W_ih, W_hh, b_ih, b_hh);
    out_kernel<<<VOCAB / 256, 256, HID * BSZ * 4>>>(lin_W, lin_b, out);
}